// round 15
// baseline (speedup 1.0000x reference)
#include <cuda_runtime.h>

// Shapes fixed by reference: d2 [16, 8192, 256] fp32
constexpr int B = 16, L = 8192, K4 = 64;
constexpr float LAM = 0.95f, OM = 0.05f;
constexpr float L8  = 0.66342043f;   // 0.95^8
constexpr float L16 = 0.44012667f;   // 0.95^16
constexpr float L24 = 0.29198906f;   // 0.95^24
constexpr float L32 = 0.19371148f;   // 0.95^32

constexpr int TR   = 8;               // steps per thread per sub-tile
constexpr int GRP  = 4;               // groups (256 thr = 64 lanes x 4)
constexpr int ST   = TR * GRP;        // 32 steps per sub-tile
constexpr int SEG  = 512;             // steps per CTA segment (row-aligned)
constexpr int NSUB = SEG / ST;        // 16 main sub-tiles
constexpr int WSUB = 5;               // warmup sub-tiles (160 steps, lam^160 ~ 2.7e-4)
constexpr int SEGR = L / SEG;         // 16 segments per row
constexpr int NCTA = B * SEGR;        // 256 CTAs
constexpr int IST  = ST * K4;         // float4 stride per sub-tile (2048)

__device__ __forceinline__ float4 f4fma(float a, float4 u, float4 v) {
    return make_float4(fmaf(a, u.x, v.x), fmaf(a, u.y, v.y),
                       fmaf(a, u.z, v.z), fmaf(a, u.w, v.w));
}
__device__ __forceinline__ float4 f4s(float a, float4 u) {
    return make_float4(a * u.x, a * u.y, a * u.z, a * u.w);
}

__device__ __forceinline__ void ldtile(float4 (&buf)[TR], const float4* __restrict__ p) {
#pragma unroll
    for (int t = 0; t < TR; ++t) buf[t] = p[t * K4];
}

// Warmup sub-tile: scan only, fold aggregate into per-group accumulator A.
// NO barrier, NO SMEM — groups stay fully decoupled.
__device__ __forceinline__ void procW(const float4 (&x)[TR], float4& A) {
    float4 z = make_float4(0.f, 0.f, 0.f, 0.f);
#pragma unroll
    for (int t = 0; t < TR; ++t) {
        z.x = fmaf(LAM, z.x, OM * x[t].x);
        z.y = fmaf(LAM, z.y, OM * x[t].y);
        z.z = fmaf(LAM, z.z, OM * x[t].z);
        z.w = fmaf(LAM, z.w, OM * x[t].w);
    }
    A = f4fma(L32, A, z);     // A = sum_i lam^{32(W-1-i)} z_i
}

// Main sub-tile: scan, combine via parity SMEM buffer (1 barrier), fixup, store.
__device__ __forceinline__ void procS(float4 (&x)[TR], float4& C,
                                      float4 (*s_agg)[K4], int lane, int s,
                                      float4* __restrict__ q) {
    float4 z = make_float4(0.f, 0.f, 0.f, 0.f);
#pragma unroll
    for (int t = 0; t < TR; ++t) {
        z.x = fmaf(LAM, z.x, OM * x[t].x);
        z.y = fmaf(LAM, z.y, OM * x[t].y);
        z.z = fmaf(LAM, z.z, OM * x[t].z);
        z.w = fmaf(LAM, z.w, OM * x[t].w);
        x[t] = z;
    }
    s_agg[s][lane] = z;
    __syncthreads();
    const float4 a0 = s_agg[0][lane], a1 = s_agg[1][lane];
    const float4 a2 = s_agg[2][lane], a3 = s_agg[3][lane];

    float4 e;                       // exact z at this group's entry (s warp-uniform)
    if      (s == 0) e = C;
    else if (s == 1) e = f4fma(L8,  C, a0);
    else if (s == 2) e = f4fma(L16, C, f4fma(L8, a0, a1));
    else             e = f4fma(L24, C, f4fma(L16, a0, f4fma(L8, a1, a2)));
    float4 cf = e;
#pragma unroll
    for (int t = 0; t < TR; ++t) {
        cf = f4s(LAM, cf);          // e * lam^(t+1)
        x[t].x += cf.x; x[t].y += cf.y; x[t].z += cf.z; x[t].w += cf.w;
        q[t * K4] = x[t];
    }
    float4 Af = f4fma(L8, f4fma(L8, f4fma(L8, a0, a1), a2), a3);
    C = f4fma(L32, C, Af);
}

__global__ __launch_bounds__(256, 2) void pft_scan(const float4* __restrict__ d2,
                                                   float4* __restrict__ out) {
    __shared__ float4 s_agg2[2][GRP][K4];   // parity ping-pong (main loop)
    __shared__ float4 s_warm[GRP][K4];      // one-shot warmup combine
    const int tid  = threadIdx.x;
    const int lane = tid & (K4 - 1);
    const int s    = tid >> 6;
    const int bid  = blockIdx.x;
    const int ct   = bid & (SEGR - 1);      // segment within row
    const int b    = bid >> 4;              // batch row

    const int w     = ct ? WSUB : 0;
    const int niter = w + NSUB;             // 21 or 16
    const long long g0 = (long long)ct * SEG - (long long)w * ST;

    const size_t thr0 = ((size_t)b * L + g0) * K4 + (size_t)s * TR * K4 + lane;
    const float4* p = d2  + thr0;
    float4*       q = out + thr0;

    float4 C = make_float4(0.f, 0.f, 0.f, 0.f);
    float4 A = make_float4(0.f, 0.f, 0.f, 0.f);
    float4 bufA[TR], bufB[TR];

    // One step of the pipeline: process sub-tile idx from buf (parity par).
    auto STEP = [&](float4 (&buf)[TR], int idx, int par) {
        if (idx < w) {
            procW(buf, A);
        } else {
            if (w && idx == w) {            // warmup -> main boundary: combine A_s
                s_warm[s][lane] = A;
                __syncthreads();
                const float4 a0 = s_warm[0][lane], a1 = s_warm[1][lane];
                const float4 a2 = s_warm[2][lane], a3 = s_warm[3][lane];
                C = f4fma(L8, f4fma(L8, f4fma(L8, a0, a1), a2), a3);
            }
            procS(buf, C, s_agg2[par], lane, s, q + (size_t)idx * IST);
        }
    };

    ldtile(bufA, p);
    int i = 0;
    while (i < niter) {
        if (i + 1 < niter) ldtile(bufB, p + (size_t)(i + 1) * IST);
        STEP(bufA, i, 0);
        if (i + 2 < niter) ldtile(bufA, p + (size_t)(i + 2) * IST);
        if (i + 1 < niter) STEP(bufB, i + 1, 1);
        i += 2;
    }
}

extern "C" void kernel_launch(void* const* d_in, const int* in_sizes, int n_in,
                              void* d_out, int out_size) {
    (void)in_sizes; (void)n_in; (void)out_size;
    const float4* d2 = (const float4*)d_in[0];
    float4* out = (float4*)d_out;

    pft_scan<<<NCTA, 256>>>(d2, out);
}

// round 17
// speedup vs baseline: 1.0052x; 1.0052x over previous
#include <cuda_runtime.h>

// Shapes fixed by reference: d2 [16, 8192, 256] fp32
constexpr int B = 16, L = 8192, K4 = 64;
constexpr float LAM = 0.95f, OM = 0.05f;
constexpr float L8  = 0.66342043f;   // 0.95^8
constexpr float L16 = 0.44012667f;   // 0.95^16
constexpr float L24 = 0.29198906f;   // 0.95^24
constexpr float L32 = 0.19371148f;   // 0.95^32

constexpr int TR   = 8;      // steps per thread per sub-tile
constexpr int GRP  = 4;      // sub-chunks per CTA (256 thr = 64 lanes x 4)
constexpr int ST   = TR * GRP;        // 32 steps per sub-tile
constexpr int SEG  = 512;             // steps per CTA segment (row-aligned)
constexpr int NSUB = SEG / ST;        // 16 main sub-tiles
constexpr int WSUB = 6;               // warmup sub-tiles (192 steps, lam^192 ~ 5e-5)
constexpr int SEGR = L / SEG;         // 16 segments per row
constexpr int NCTA = B * SEGR;        // 256 CTAs
constexpr int IST  = ST * K4;         // float4 stride per sub-tile (2048)

__device__ __forceinline__ float4 f4fma(float a, float4 u, float4 v) {
    return make_float4(fmaf(a, u.x, v.x), fmaf(a, u.y, v.y),
                       fmaf(a, u.z, v.z), fmaf(a, u.w, v.w));
}
__device__ __forceinline__ float4 f4s(float a, float4 u) {
    return make_float4(a * u.x, a * u.y, a * u.z, a * u.w);
}

__device__ __forceinline__ void ldtile(float4 (&buf)[TR], const float4* __restrict__ p) {
#pragma unroll
    for (int t = 0; t < TR; ++t) buf[t] = p[t * K4];
}

// Scan one sub-tile; s_agg is the parity-selected buffer for THIS sub-tile.
// Single barrier per call: buffer reuse is 2 calls away with a barrier between.
__device__ __forceinline__ void proc(float4 (&x)[TR], float4& C,
                                     float4 (*s_agg)[K4], int lane, int s,
                                     bool doStore, float4* __restrict__ q) {
    float4 z = make_float4(0.f, 0.f, 0.f, 0.f);
#pragma unroll
    for (int t = 0; t < TR; ++t) {
        z.x = fmaf(LAM, z.x, OM * x[t].x);
        z.y = fmaf(LAM, z.y, OM * x[t].y);
        z.z = fmaf(LAM, z.z, OM * x[t].z);
        z.w = fmaf(LAM, z.w, OM * x[t].w);
        x[t] = z;
    }
    s_agg[s][lane] = z;
    __syncthreads();
    const float4 a0 = s_agg[0][lane], a1 = s_agg[1][lane];
    const float4 a2 = s_agg[2][lane], a3 = s_agg[3][lane];

    if (doStore) {
        float4 e;                    // exact z at this group's entry (s warp-uniform)
        if      (s == 0) e = C;
        else if (s == 1) e = f4fma(L8,  C, a0);
        else if (s == 2) e = f4fma(L16, C, f4fma(L8, a0, a1));
        else             e = f4fma(L24, C, f4fma(L16, a0, f4fma(L8, a1, a2)));
        float4 cf = e;
#pragma unroll
        for (int t = 0; t < TR; ++t) {
            cf = f4s(LAM, cf);       // e * lam^(t+1)
            x[t].x += cf.x; x[t].y += cf.y; x[t].z += cf.z; x[t].w += cf.w;
            q[t * K4] = x[t];
        }
    }
    // running carry: C' = lam^32*C + (a3 + L8*a2 + L16*a1 + L24*a0)
    float4 Af = f4fma(L8, f4fma(L8, f4fma(L8, a0, a1), a2), a3);
    C = f4fma(L32, C, Af);
}

__global__ __launch_bounds__(256, 2) void pft_scan(const float4* __restrict__ d2,
                                                   float4* __restrict__ out) {
    __shared__ float4 s_agg2[2][GRP][K4];     // parity ping-pong buffers
    const int tid  = threadIdx.x;
    const int lane = tid & (K4 - 1);
    const int s    = tid >> 6;
    const int bid  = blockIdx.x;
    const int ct   = bid & (SEGR - 1);        // segment within row
    const int b    = bid >> 4;                // batch row

    const int w     = ct ? WSUB : 0;          // warmup sub-tiles
    const int niter = w + NSUB;               // 22 or 16 (both even)
    const long long g0 = (long long)ct * SEG - (long long)w * ST;

    const size_t thr0 = ((size_t)b * L + g0) * K4 + (size_t)s * TR * K4 + lane;
    const float4* p = d2  + thr0;
    float4*       q = out + thr0;

    float4 C = make_float4(0.f, 0.f, 0.f, 0.f);
    float4 bufA[TR], bufB[TR];

    ldtile(bufA, p);                          // preload sub-tile 0
    for (int i = 0; i < niter; i += 2) {
        ldtile(bufB, p + (size_t)(i + 1) * IST);      // i+1 < niter (niter even)
        proc(bufA, C, s_agg2[0], lane, s, i >= w, q + (size_t)i * IST);
        if (i + 2 < niter) ldtile(bufA, p + (size_t)(i + 2) * IST);
        proc(bufB, C, s_agg2[1], lane, s, i + 1 >= w, q + (size_t)(i + 1) * IST);
    }
}

extern "C" void kernel_launch(void* const* d_in, const int* in_sizes, int n_in,
                              void* d_out, int out_size) {
    (void)in_sizes; (void)n_in; (void)out_size;
    const float4* d2 = (const float4*)d_in[0];
    float4* out = (float4*)d_out;

    pft_scan<<<NCTA, 256>>>(d2, out);
}